// round 5
// baseline (speedup 1.0000x reference)
#include <cuda_runtime.h>
#include <math.h>

#define N_   32
#define C_   256
#define HW_  4096
#define G_   4
#define D_   64
#define MTOT 131072.0f
#define EPSW 1e-5f
#define LNEPS 1e-5f

typedef unsigned long long ull;

__device__ __forceinline__ void fma2(ull& d, ull a, ull b) {
    asm("fma.rn.f32x2 %0, %1, %2, %0;" : "+l"(d) : "l"(a), "l"(b));
}
__device__ __forceinline__ void add2(ull& d, ull a) {
    asm("add.rn.f32x2 %0, %0, %1;" : "+l"(d) : "l"(a));
}
__device__ __forceinline__ float2 u2f(ull v) {
    float2 r;
    asm("mov.b64 {%0,%1}, %2;" : "=f"(r.x), "=f"(r.y) : "l"(v));
    return r;
}
__device__ __forceinline__ void cpa16(void* sdst, const void* gsrc) {
    unsigned s = (unsigned)__cvta_generic_to_shared(sdst);
    asm volatile("cp.async.ca.shared.global [%0], [%1], 16;" :: "r"(s), "l"(gsrc));
}
__device__ __forceinline__ void cpa8(void* sdst, const void* gsrc) {
    unsigned s = (unsigned)__cvta_generic_to_shared(sdst);
    asm volatile("cp.async.ca.shared.global [%0], [%1], 8;" :: "r"(s), "l"(gsrc));
}
#define CP_COMMIT() asm volatile("cp.async.commit_group;")
#define CP_WAIT0()  asm volatile("cp.async.wait_group 0;")

// ---------------- device scratch ----------------
__device__ float d_sum  [N_*C_];
__device__ float d_sumsq[N_*C_];
__device__ float d_gram [G_*D_*D_];
__device__ float d_xv   [N_*C_];
__device__ float d_a    [N_*C_];
__device__ float d_mu   [C_];
__device__ float d_wP   [G_*D_*D_];
__device__ float d_w;
__device__ float d_coef;

// ---------------- K0: zero accumulators ----------------
__global__ void k_zero() {
    int i = blockIdx.x * blockDim.x + threadIdx.x;
    if (i < N_*C_) { d_sum[i] = 0.0f; d_sumsq[i] = 0.0f; }
    if (i < G_*D_*D_) d_gram[i] = 0.0f;
}

// ---------------- K1: gram + fused row stats -------------------------------
// grid (chunk=4, n=32, g=4), 256 thr. tile = 128 positions x 64 channels.
// Rows padded to 130 floats: row stride == 2 banks -> tx-indexed LDS.64
// conflict-free. 8B cp.async (rows are 8B-aligned only).
__global__ void __launch_bounds__(256) k_gram(const float* __restrict__ X) {
    extern __shared__ __align__(16) float gsm[];
    float* xs0 = gsm;                 // 64*130
    float* xs1 = gsm + 8320;
    __shared__ float rs[256], rs2[256];
    int chunk = blockIdx.x, n = blockIdx.y, g = blockIdx.z;
    int tid = threadIdx.x;
    int tx = tid & 15, ty = tid >> 4;
    int cs = tid & 63, q = tid >> 6;
    const float* base = X + ((size_t)n * C_ + (size_t)g * D_) * HW_ + chunk * 1024;

    ull acc[4][4] = {};
    ull s_acc = 0ull, s2_acc = 0ull;
    float* bufs[2] = { xs0, xs1 };

    {   // prologue: tile 0 -> buf 0
        #pragma unroll
        for (int k = 0; k < 16; ++k) {
            int pos = tid + k * 256;
            int c = pos >> 6, s8 = pos & 63;
            cpa8(xs0 + c * 130 + s8 * 2, base + (size_t)c * HW_ + s8 * 2);
        }
        CP_COMMIT();
    }

    int buf = 0;
    for (int t = 0; t < 8; ++t) {            // 8 tiles of 128 positions
        CP_WAIT0();
        __syncthreads();
        if (t < 7) {
            const float* src = base + (t + 1) * 128;
            float* db = bufs[buf ^ 1];
            #pragma unroll
            for (int k = 0; k < 16; ++k) {
                int pos = tid + k * 256;
                int c = pos >> 6, s8 = pos & 63;
                cpa8(db + c * 130 + s8 * 2, src + (size_t)c * HW_ + s8 * 2);
            }
            CP_COMMIT();
        }
        const ull* xa = (const ull*)bufs[buf];     // row stride 65 ull
        #pragma unroll 4
        for (int u = 0; u < 64; ++u) {
            ull a0 = xa[(ty     )*65 + u], a1 = xa[(ty + 16)*65 + u];
            ull a2 = xa[(ty + 32)*65 + u], a3 = xa[(ty + 48)*65 + u];
            ull b0 = xa[(tx     )*65 + u], b1 = xa[(tx + 16)*65 + u];
            ull b2 = xa[(tx + 32)*65 + u], b3 = xa[(tx + 48)*65 + u];
            fma2(acc[0][0], a0, b0); fma2(acc[0][1], a0, b1);
            fma2(acc[0][2], a0, b2); fma2(acc[0][3], a0, b3);
            fma2(acc[1][0], a1, b0); fma2(acc[1][1], a1, b1);
            fma2(acc[1][2], a1, b2); fma2(acc[1][3], a1, b3);
            fma2(acc[2][0], a2, b0); fma2(acc[2][1], a2, b1);
            fma2(acc[2][2], a2, b2); fma2(acc[2][3], a2, b3);
            fma2(acc[3][0], a3, b0); fma2(acc[3][1], a3, b1);
            fma2(acc[3][2], a3, b2); fma2(acc[3][3], a3, b3);
        }
        #pragma unroll
        for (int u = 16 * q; u < 16 * q + 16; ++u) {
            ull v = xa[cs * 65 + u];
            add2(s_acc, v);
            fma2(s2_acc, v, v);
        }
        buf ^= 1;
    }

    float2 sv = u2f(s_acc), s2v = u2f(s2_acc);
    rs[tid] = sv.x + sv.y; rs2[tid] = s2v.x + s2v.y;
    __syncthreads();
    if (tid < 64) {
        float a = rs[tid] + rs[tid+64] + rs[tid+128] + rs[tid+192];
        float b = rs2[tid] + rs2[tid+64] + rs2[tid+128] + rs2[tid+192];
        atomicAdd(&d_sum  [n * C_ + g * 64 + tid], a);
        atomicAdd(&d_sumsq[n * C_ + g * 64 + tid], b);
    }
    float* gp = d_gram + g * D_ * D_;
    #pragma unroll
    for (int i = 0; i < 4; ++i)
        #pragma unroll
        for (int j = 0; j < 4; ++j) {
            float2 f = u2f(acc[i][j]);
            atomicAdd(&gp[(ty + 16*i) * D_ + tx + 16*j], f.x + f.y);
        }
}

// ---------------- K2: xvar, scale, mu, w (tiny) ----------------
__global__ void k_prep(const float* __restrict__ xw) {
    __shared__ float red[256];
    int tid = threadIdx.x;
    float acc = 0.0f;
    for (int i = tid; i < N_*C_; i += 256) {
        float s = d_sum[i], s2 = d_sumsq[i];
        float v = (s2 - s * s * (1.0f / HW_)) * (1.0f / (HW_ - 1));
        d_xv[i] = v;
        acc += v;
    }
    red[tid] = acc;
    __syncthreads();
    for (int off = 128; off; off >>= 1) {
        if (tid < off) red[tid] += red[tid + off];
        __syncthreads();
    }
    float m = 0.0f;
    #pragma unroll
    for (int n = 0; n < N_; ++n) m += d_sum[n * C_ + tid];
    d_mu[tid] = m * (1.0f / MTOT);
    if (tid == 0) {
        float w = 1.0f / (1.0f + expf(-xw[0]));
        d_w = w;
        d_coef = (1.0f - w) / sqrtf(red[0] * (1.0f / (N_*C_)));
    }
}

// ---------------- K3: fused newton (blocks 0-3) + mlp (blocks 4-35) --------
__device__ __forceinline__ void mm64t(float* Cm, const float* A, const float* B,
                                      int tx, int ty) {
    float acc[2][4] = {};
    #pragma unroll 4
    for (int k = 0; k < 64; ++k) {
        float a0 = A[ty*66 + k], a1 = A[(ty + 32)*66 + k];
        float b0 = B[k*66 + tx],      b1 = B[k*66 + tx + 16];
        float b2 = B[k*66 + tx + 32], b3 = B[k*66 + tx + 48];
        acc[0][0] += a0*b0; acc[0][1] += a0*b1; acc[0][2] += a0*b2; acc[0][3] += a0*b3;
        acc[1][0] += a1*b0; acc[1][1] += a1*b1; acc[1][2] += a1*b2; acc[1][3] += a1*b3;
    }
    #pragma unroll
    for (int i = 0; i < 2; ++i)
        #pragma unroll
        for (int j = 0; j < 4; ++j)
            Cm[(ty + 32*i)*66 + tx + 16*j] = acc[i][j];
}

__global__ void __launch_bounds__(512) k_tail(const float* __restrict__ fc1,
                                              const float* __restrict__ lng,
                                              const float* __restrict__ lnb,
                                              const float* __restrict__ fc2) {
    extern __shared__ float sm[];
    int blk = blockIdx.x, tid = threadIdx.x;

    if (blk < 4) {
        // ---- Newton-Schulz for group g = blk ----
        float* SigN = sm;
        float* P    = sm + 4224;
        float* T1   = sm + 8448;
        float* T2   = sm + 12672;
        __shared__ float s_invtr;
        int g = blk;
        int tx = tid & 15, ty = tid >> 4;
        float w = d_w;

        for (int t = 0; t < 8; ++t) {
            int idx = tid + t * 512;
            int d = idx >> 6, e = idx & 63;
            float v = EPSW * (d_gram[g*4096 + idx] - MTOT * d_mu[g*64 + d] * d_mu[g*64 + e]);
            if (d == e) v += 1.0f / MTOT;
            T1[d*66 + e] = v;
        }
        __syncthreads();
        if (tid == 0) {
            float tr = 0.0f;
            for (int d = 0; d < 64; ++d) tr += T1[d*66 + d];
            s_invtr = 1.0f / tr;
        }
        __syncthreads();
        float invtr = s_invtr;
        for (int t = 0; t < 8; ++t) {
            int idx = tid + t * 512;
            int d = idx >> 6, e = idx & 63;
            float s = T1[d*66 + e] * invtr;
            SigN[d*66 + e] = s;
            P[d*66 + e] = 1.5f * s + ((d == e) ? -0.5f : 0.0f);
        }
        __syncthreads();
        for (int it = 0; it < 2; ++it) {
            mm64t(T1, P, P, tx, ty);     __syncthreads();
            mm64t(T2, T1, P, tx, ty);    __syncthreads();
            mm64t(T1, T2, SigN, tx, ty); __syncthreads();
            for (int t = 0; t < 8; ++t) {
                int idx = tid + t * 512;
                int d = idx >> 6, e = idx & 63;
                P[d*66 + e] = -0.5f * P[d*66 + e] + 1.5f * T1[d*66 + e];
            }
            __syncthreads();
        }
        for (int t = 0; t < 8; ++t) {
            int idx = tid + t * 512;
            int d = idx >> 6, e = idx & 63;
            d_wP[g*4096 + idx] = w * P[d*66 + e];
        }
    } else {
        // ---- MLP for batch row n = blk - 4 (coalesced warp-per-output) ----
        int n = blk - 4;
        float* xv = sm;          // 256
        float* h  = sm + 256;    // 64
        __shared__ float s_mu, s_inv;
        int w = tid >> 5, lane = tid & 31;

        if (tid < 256) xv[tid] = d_xv[n * C_ + tid];
        __syncthreads();

        // fc1: 16 warps x 4 rows; lanes sweep C coalesced
        #pragma unroll
        for (int jj = 0; jj < 4; ++jj) {
            int j = w * 4 + jj;
            float a = 0.0f;
            #pragma unroll
            for (int s = 0; s < 8; ++s)
                a += fc1[j * C_ + lane + 32 * s] * xv[lane + 32 * s];
            #pragma unroll
            for (int o = 16; o; o >>= 1) a += __shfl_xor_sync(0xffffffffu, a, o);
            if (lane == 0) h[j] = a;
        }
        __syncthreads();

        if (w == 0) {
            float v0 = h[lane], v1 = h[lane + 32];
            float s = v0 + v1, s2 = v0*v0 + v1*v1;
            #pragma unroll
            for (int o = 16; o; o >>= 1) {
                s  += __shfl_xor_sync(0xffffffffu, s,  o);
                s2 += __shfl_xor_sync(0xffffffffu, s2, o);
            }
            if (lane == 0) {
                float mu = s * (1.0f / D_);
                float var = s2 * (1.0f / D_) - mu * mu;
                s_mu = mu; s_inv = rsqrtf(var + LNEPS);
            }
        }
        __syncthreads();
        if (tid < 64) {
            float v = (h[tid] - s_mu) * s_inv * lng[tid] + lnb[tid];
            h[tid] = v > 0.0f ? v : 0.0f;
        }
        __syncthreads();

        // fc2: warp handles c = w + 16k; lanes sweep D coalesced
        float coef = d_coef;
        #pragma unroll
        for (int k = 0; k < 16; ++k) {
            int c = w + 16 * k;
            float a = fc2[c * D_ + lane] * h[lane]
                    + fc2[c * D_ + lane + 32] * h[lane + 32];
            #pragma unroll
            for (int o = 16; o; o >>= 1) a += __shfl_xor_sync(0xffffffffu, a, o);
            if (lane == 0) d_a[n * C_ + c] = coef / (1.0f + expf(-a));
        }
    }
}

// ---------------- K5: out = (wP[g] + diag(a[n])) @ x -----------------------
// grid (chunk=4, n=32, g=4), 256 thr. tile = 128 positions; thread tile 4d x 8s.
// xs rows 132 floats (16B-aligned, tx-indexed loads conflict-free).
// Md: M duplicated pairs, row stride 130 floats (broadcast LDS.64).
__global__ void __launch_bounds__(256) k_apply(const float* __restrict__ X,
                                               float* __restrict__ out) {
    extern __shared__ __align__(16) float sm2[];
    float* xs0 = sm2;                 // 64*132 = 8448
    float* xs1 = sm2 + 8448;
    float* Md  = sm2 + 16896;         // 64*130 = 8320
    int chunk = blockIdx.x, n = blockIdx.y, g = blockIdx.z;
    int tid = threadIdx.x;
    int tx = tid & 15, ty = tid >> 4;

    const float* base  = X   + ((size_t)n * C_ + (size_t)g * D_) * HW_ + chunk * 1024;
    float*       obase = out + ((size_t)n * C_ + (size_t)g * D_) * HW_ + chunk * 1024;

    {   // prologue copy tile 0
        #pragma unroll
        for (int k = 0; k < 8; ++k) {
            int pos = tid + k * 256;
            int c = pos >> 5, s4 = pos & 31;
            cpa16(xs0 + c * 132 + s4 * 4, base + (size_t)c * HW_ + s4 * 4);
        }
        CP_COMMIT();
    }
    // build Md while copy is in flight
    for (int t = 0; t < 16; ++t) {
        int idx = tid + t * 256;
        int d = idx & 63, e = idx >> 6;
        float v = d_wP[g*4096 + d * 64 + e];
        if (d == e) v += d_a[n * C_ + g * 64 + d];
        *(float2*)&Md[e * 130 + 2 * d] = make_float2(v, v);
    }

    float* bufs[2] = { xs0, xs1 };
    int buf = 0;
    for (int t = 0; t < 8; ++t) {
        CP_WAIT0();
        __syncthreads();
        if (t < 7) {
            const float* src = base + (t + 1) * 128;
            float* db = bufs[buf ^ 1];
            #pragma unroll
            for (int k = 0; k < 8; ++k) {
                int pos = tid + k * 256;
                int c = pos >> 5, s4 = pos & 31;
                cpa16(db + c * 132 + s4 * 4, src + (size_t)c * HW_ + s4 * 4);
            }
            CP_COMMIT();
        }
        ull acc[4][4] = {};
        const ull* xa = (const ull*)bufs[buf];   // row stride 66 ull
        const ull* Ma = (const ull*)Md;          // row stride 65 ull
        #pragma unroll 4
        for (int e = 0; e < 64; ++e) {
            ull b0 = xa[e*66 + tx],      b1 = xa[e*66 + tx + 16];
            ull b2 = xa[e*66 + tx + 32], b3 = xa[e*66 + tx + 48];
            ull a0 = Ma[e*65 + ty],      a1 = Ma[e*65 + ty + 16];
            ull a2 = Ma[e*65 + ty + 32], a3 = Ma[e*65 + ty + 48];
            fma2(acc[0][0], a0, b0); fma2(acc[0][1], a0, b1);
            fma2(acc[0][2], a0, b2); fma2(acc[0][3], a0, b3);
            fma2(acc[1][0], a1, b0); fma2(acc[1][1], a1, b1);
            fma2(acc[1][2], a1, b2); fma2(acc[1][3], a1, b3);
            fma2(acc[2][0], a2, b0); fma2(acc[2][1], a2, b1);
            fma2(acc[2][2], a2, b2); fma2(acc[2][3], a2, b3);
            fma2(acc[3][0], a3, b0); fma2(acc[3][1], a3, b1);
            fma2(acc[3][2], a3, b2); fma2(acc[3][3], a3, b3);
        }
        float* dst = obase + t * 128;
        #pragma unroll
        for (int i = 0; i < 4; ++i) {
            int d = ty + 16 * i;
            float* drow = dst + (size_t)d * HW_;
            #pragma unroll
            for (int j = 0; j < 4; ++j)
                *(float2*)(drow + (tx + 16*j) * 2) = u2f(acc[i][j]);
        }
        buf ^= 1;
    }
}

// ---------------- launch ----------------
extern "C" void kernel_launch(void* const* d_in, const int* in_sizes, int n_in,
                              void* d_out, int out_size) {
    const float* X   = (const float*)d_in[0];
    const float* fc1 = (const float*)d_in[1];
    const float* lng = (const float*)d_in[2];
    const float* lnb = (const float*)d_in[3];
    const float* fc2 = (const float*)d_in[4];
    const float* xw  = (const float*)d_in[5];
    float* out = (float*)d_out;

    static bool attr_set = false;
    if (!attr_set) {
        cudaFuncSetAttribute(k_gram,  cudaFuncAttributeMaxDynamicSharedMemorySize, 66560);
        cudaFuncSetAttribute(k_tail,  cudaFuncAttributeMaxDynamicSharedMemorySize, 69632);
        cudaFuncSetAttribute(k_apply, cudaFuncAttributeMaxDynamicSharedMemorySize, 101376);
        attr_set = true;
    }

    k_zero <<<64, 256>>>();
    k_gram <<<dim3(4, 32, 4), 256, 66560>>>(X);
    k_prep <<<1, 256>>>(xw);
    k_tail <<<36, 512, 67584>>>(fc1, lng, lnb, fc2);
    k_apply<<<dim3(4, 32, 4), 256, 101376>>>(X, out);
}

// round 6
// speedup vs baseline: 1.1459x; 1.1459x over previous
#include <cuda_runtime.h>
#include <math.h>

#define N_   32
#define C_   256
#define HW_  4096
#define G_   4
#define D_   64
#define MTOT 131072.0f
#define EPSW 1e-5f
#define LNEPS 1e-5f

typedef unsigned long long ull;

__device__ __forceinline__ void fma2(ull& d, ull a, ull b) {
    asm("fma.rn.f32x2 %0, %1, %2, %0;" : "+l"(d) : "l"(a), "l"(b));
}
__device__ __forceinline__ void add2(ull& d, ull a) {
    asm("add.rn.f32x2 %0, %0, %1;" : "+l"(d) : "l"(a));
}
__device__ __forceinline__ float2 u2f(ull v) {
    float2 r;
    asm("mov.b64 {%0,%1}, %2;" : "=f"(r.x), "=f"(r.y) : "l"(v));
    return r;
}
__device__ __forceinline__ void cpa16(void* sdst, const void* gsrc) {
    unsigned s = (unsigned)__cvta_generic_to_shared(sdst);
    asm volatile("cp.async.ca.shared.global [%0], [%1], 16;" :: "r"(s), "l"(gsrc));
}
__device__ __forceinline__ void cpa8(void* sdst, const void* gsrc) {
    unsigned s = (unsigned)__cvta_generic_to_shared(sdst);
    asm volatile("cp.async.ca.shared.global [%0], [%1], 8;" :: "r"(s), "l"(gsrc));
}
#define CP_COMMIT() asm volatile("cp.async.commit_group;")
#define CP_WAIT0()  asm volatile("cp.async.wait_group 0;")

// ---------------- device scratch ----------------
__device__ float d_sum  [N_*C_];
__device__ float d_sumsq[N_*C_];
__device__ float d_gram [G_*D_*D_];
__device__ float d_a    [N_*C_];
__device__ float d_wP   [G_*D_*D_];

// ---------------- K0: zero accumulators ----------------
__global__ void k_zero() {
    int i = blockIdx.x * blockDim.x + threadIdx.x;
    if (i < N_*C_) { d_sum[i] = 0.0f; d_sumsq[i] = 0.0f; }
    if (i < G_*D_*D_) d_gram[i] = 0.0f;
}

// ---------------- K1: gram + fused row stats -------------------------------
// grid (chunk=4, n=32, g=4), 256 thr, 64-pos tiles, double-buffered cp.async.
// Rows padded to 66 floats: row stride == 2 banks -> distinct-address LDS.64
// (b-loads) conflict-free. 8B cp.async (rows only 8B-aligned).
__global__ void __launch_bounds__(256) k_gram(const float* __restrict__ X) {
    __shared__ __align__(16) float xs[2][D_ * 66];   // 33792 B
    __shared__ float rs[256], rs2[256];
    int chunk = blockIdx.x, n = blockIdx.y, g = blockIdx.z;
    int tid = threadIdx.x;
    int tx = tid & 15, ty = tid >> 4;
    int cs = tid & 63, q = tid >> 6;
    const float* base = X + ((size_t)n * C_ + (size_t)g * D_) * HW_ + chunk * 1024;

    ull acc[4][4] = {};
    ull s_acc = 0ull, s2_acc = 0ull;

    {   // prologue: tile 0 -> buf 0
        #pragma unroll
        for (int k = 0; k < 8; ++k) {
            int pos = tid + k * 256;
            int c = pos >> 5, s8 = pos & 31;
            cpa8(&xs[0][c * 66 + s8 * 2], base + (size_t)c * HW_ + s8 * 2);
        }
        CP_COMMIT();
    }

    int buf = 0;
    for (int t = 0; t < 16; ++t) {
        CP_WAIT0();
        __syncthreads();
        if (t < 15) {
            const float* src = base + (t + 1) * 64;
            #pragma unroll
            for (int k = 0; k < 8; ++k) {
                int pos = tid + k * 256;
                int c = pos >> 5, s8 = pos & 31;
                cpa8(&xs[buf ^ 1][c * 66 + s8 * 2], src + (size_t)c * HW_ + s8 * 2);
            }
            CP_COMMIT();
        }
        const ull* xa = (const ull*)xs[buf];        // row stride 33 ull
        #pragma unroll 4
        for (int u = 0; u < 32; ++u) {
            ull a0 = xa[(ty     )*33 + u], a1 = xa[(ty + 16)*33 + u];
            ull a2 = xa[(ty + 32)*33 + u], a3 = xa[(ty + 48)*33 + u];
            ull b0 = xa[(tx     )*33 + u], b1 = xa[(tx + 16)*33 + u];
            ull b2 = xa[(tx + 32)*33 + u], b3 = xa[(tx + 48)*33 + u];
            fma2(acc[0][0], a0, b0); fma2(acc[0][1], a0, b1);
            fma2(acc[0][2], a0, b2); fma2(acc[0][3], a0, b3);
            fma2(acc[1][0], a1, b0); fma2(acc[1][1], a1, b1);
            fma2(acc[1][2], a1, b2); fma2(acc[1][3], a1, b3);
            fma2(acc[2][0], a2, b0); fma2(acc[2][1], a2, b1);
            fma2(acc[2][2], a2, b2); fma2(acc[2][3], a2, b3);
            fma2(acc[3][0], a3, b0); fma2(acc[3][1], a3, b1);
            fma2(acc[3][2], a3, b2); fma2(acc[3][3], a3, b3);
        }
        #pragma unroll
        for (int u = 8 * q; u < 8 * q + 8; ++u) {
            ull v = xa[cs * 33 + u];
            add2(s_acc, v);
            fma2(s2_acc, v, v);
        }
        buf ^= 1;
    }

    float2 sv = u2f(s_acc), s2v = u2f(s2_acc);
    rs[tid] = sv.x + sv.y; rs2[tid] = s2v.x + s2v.y;
    __syncthreads();
    if (tid < 64) {
        float a = rs[tid] + rs[tid+64] + rs[tid+128] + rs[tid+192];
        float b = rs2[tid] + rs2[tid+64] + rs2[tid+128] + rs2[tid+192];
        atomicAdd(&d_sum  [n * C_ + g * 64 + tid], a);
        atomicAdd(&d_sumsq[n * C_ + g * 64 + tid], b);
    }
    float* gp = d_gram + g * D_ * D_;
    #pragma unroll
    for (int i = 0; i < 4; ++i)
        #pragma unroll
        for (int j = 0; j < 4; ++j) {
            float2 f = u2f(acc[i][j]);
            atomicAdd(&gp[(ty + 16*i) * D_ + tx + 16*j], f.x + f.y);
        }
}

// ---------------- K2: fused newton (blocks 0-3) + mlp (blocks 4-35) --------
// Self-contained: each block recomputes the tiny prep stats it needs.
__device__ __forceinline__ void mm64t(float* Cm, const float* A, const float* B,
                                      int tx, int ty) {
    float acc[2][4] = {};
    #pragma unroll 4
    for (int k = 0; k < 64; ++k) {
        float a0 = A[ty*66 + k], a1 = A[(ty + 32)*66 + k];
        float b0 = B[k*66 + tx],      b1 = B[k*66 + tx + 16];
        float b2 = B[k*66 + tx + 32], b3 = B[k*66 + tx + 48];
        acc[0][0] += a0*b0; acc[0][1] += a0*b1; acc[0][2] += a0*b2; acc[0][3] += a0*b3;
        acc[1][0] += a1*b0; acc[1][1] += a1*b1; acc[1][2] += a1*b2; acc[1][3] += a1*b3;
    }
    #pragma unroll
    for (int i = 0; i < 2; ++i)
        #pragma unroll
        for (int j = 0; j < 4; ++j)
            Cm[(ty + 32*i)*66 + tx + 16*j] = acc[i][j];
}

__global__ void __launch_bounds__(512) k_tail(const float* __restrict__ fc1,
                                              const float* __restrict__ lng,
                                              const float* __restrict__ lnb,
                                              const float* __restrict__ fc2,
                                              const float* __restrict__ xw) {
    extern __shared__ float sm[];
    int blk = blockIdx.x, tid = threadIdx.x;
    float w = 1.0f / (1.0f + expf(-xw[0]));

    if (blk < 4) {
        // ---- Newton-Schulz for group g = blk ----
        float* SigN = sm;
        float* P    = sm + 4224;
        float* T1   = sm + 8448;
        float* T2   = sm + 12672;
        __shared__ float mu_s[64];
        __shared__ float s_invtr;
        int g = blk;
        int tx = tid & 15, ty = tid >> 4;

        if (tid < 64) {                      // channel means for this group
            float m = 0.0f;
            #pragma unroll
            for (int n = 0; n < N_; ++n) m += d_sum[n * C_ + g * 64 + tid];
            mu_s[tid] = m * (1.0f / MTOT);
        }
        __syncthreads();

        for (int t = 0; t < 8; ++t) {
            int idx = tid + t * 512;
            int d = idx >> 6, e = idx & 63;
            float v = EPSW * (d_gram[g*4096 + idx] - MTOT * mu_s[d] * mu_s[e]);
            if (d == e) v += 1.0f / MTOT;
            T1[d*66 + e] = v;
        }
        __syncthreads();
        if (tid == 0) {
            float tr = 0.0f;
            for (int d = 0; d < 64; ++d) tr += T1[d*66 + d];
            s_invtr = 1.0f / tr;
        }
        __syncthreads();
        float invtr = s_invtr;
        for (int t = 0; t < 8; ++t) {        // P1 = -0.5I + 1.5 SigN (P0 = I)
            int idx = tid + t * 512;
            int d = idx >> 6, e = idx & 63;
            float s = T1[d*66 + e] * invtr;
            SigN[d*66 + e] = s;
            P[d*66 + e] = 1.5f * s + ((d == e) ? -0.5f : 0.0f);
        }
        __syncthreads();
        for (int it = 0; it < 2; ++it) {
            mm64t(T1, P, P, tx, ty);     __syncthreads();
            mm64t(T2, T1, P, tx, ty);    __syncthreads();
            mm64t(T1, T2, SigN, tx, ty); __syncthreads();
            for (int t = 0; t < 8; ++t) {
                int idx = tid + t * 512;
                int d = idx >> 6, e = idx & 63;
                P[d*66 + e] = -0.5f * P[d*66 + e] + 1.5f * T1[d*66 + e];
            }
            __syncthreads();
        }
        for (int t = 0; t < 8; ++t) {
            int idx = tid + t * 512;
            int d = idx >> 6, e = idx & 63;
            d_wP[g*4096 + idx] = w * P[d*66 + e];
        }
    } else {
        // ---- MLP for batch row n = blk - 4 ----
        int n = blk - 4;
        float* xv  = sm;          // 256
        float* h   = sm + 256;    // 64
        float* red = sm + 320;    // 512
        __shared__ float s_mu, s_inv, s_coef;
        int wi = tid >> 5, lane = tid & 31;

        // global var-mean (for scale) + own-row vars
        float acc = 0.0f;
        for (int i = tid; i < N_*C_; i += 512) {
            float s = d_sum[i], s2 = d_sumsq[i];
            acc += (s2 - s * s * (1.0f / HW_)) * (1.0f / (HW_ - 1));
        }
        red[tid] = acc;
        if (tid < 256) {
            float s = d_sum[n * C_ + tid], s2 = d_sumsq[n * C_ + tid];
            xv[tid] = (s2 - s * s * (1.0f / HW_)) * (1.0f / (HW_ - 1));
        }
        __syncthreads();
        for (int off = 256; off; off >>= 1) {
            if (tid < off) red[tid] += red[tid + off];
            __syncthreads();
        }
        if (tid == 0)
            s_coef = (1.0f - w) / sqrtf(red[0] * (1.0f / (N_*C_)));

        // fc1: 16 warps x 4 rows; lanes sweep C coalesced
        #pragma unroll
        for (int jj = 0; jj < 4; ++jj) {
            int j = wi * 4 + jj;
            float a = 0.0f;
            #pragma unroll
            for (int s = 0; s < 8; ++s)
                a += fc1[j * C_ + lane + 32 * s] * xv[lane + 32 * s];
            #pragma unroll
            for (int o = 16; o; o >>= 1) a += __shfl_xor_sync(0xffffffffu, a, o);
            if (lane == 0) h[j] = a;
        }
        __syncthreads();

        if (wi == 0) {
            float v0 = h[lane], v1 = h[lane + 32];
            float s = v0 + v1, s2 = v0*v0 + v1*v1;
            #pragma unroll
            for (int o = 16; o; o >>= 1) {
                s  += __shfl_xor_sync(0xffffffffu, s,  o);
                s2 += __shfl_xor_sync(0xffffffffu, s2, o);
            }
            if (lane == 0) {
                float mu = s * (1.0f / D_);
                float var = s2 * (1.0f / D_) - mu * mu;
                s_mu = mu; s_inv = rsqrtf(var + LNEPS);
            }
        }
        __syncthreads();
        if (tid < 64) {
            float v = (h[tid] - s_mu) * s_inv * lng[tid] + lnb[tid];
            h[tid] = v > 0.0f ? v : 0.0f;
        }
        __syncthreads();

        // fc2: warp handles c = wi + 16k; lanes sweep D coalesced
        float coef = s_coef;
        #pragma unroll
        for (int k = 0; k < 16; ++k) {
            int c = wi + 16 * k;
            float a = fc2[c * D_ + lane] * h[lane]
                    + fc2[c * D_ + lane + 32] * h[lane + 32];
            #pragma unroll
            for (int o = 16; o; o >>= 1) a += __shfl_xor_sync(0xffffffffu, a, o);
            if (lane == 0) d_a[n * C_ + c] = coef / (1.0f + expf(-a));
        }
    }
}

// ---------------- K3: out = (wP[g] + diag(a[n])) @ x -----------------------
// grid (chunk=8, n=32, g=4), 256 thr, 64-pos tiles, 4d x 4s thread tile.
// xs rows 68 floats (16B-aligned cp.async; b-loads conflict-free: banks 4e+2tx).
// Md: M duplicated pairs, row stride 130 floats (broadcast LDS.64).
__global__ void __launch_bounds__(256) k_apply(const float* __restrict__ X,
                                               float* __restrict__ out) {
    extern __shared__ __align__(16) float sm2[];
    float* xs0 = sm2;
    float* xs1 = sm2 + 4352;
    float* Md  = sm2 + 8704;
    int chunk = blockIdx.x, n = blockIdx.y, g = blockIdx.z;
    int tid = threadIdx.x;
    int tx = tid & 15, ty = tid >> 4;

    const float* base  = X   + ((size_t)n * C_ + (size_t)g * D_) * HW_ + chunk * 512;
    float*       obase = out + ((size_t)n * C_ + (size_t)g * D_) * HW_ + chunk * 512;

    {   // prologue copy tile 0
        #pragma unroll
        for (int k = 0; k < 4; ++k) {
            int pos = tid + k * 256;
            int c = pos >> 4, s4 = pos & 15;
            cpa16(xs0 + c * 68 + s4 * 4, base + (size_t)c * HW_ + s4 * 4);
        }
        CP_COMMIT();
    }
    // build Md while copy 0 is in flight
    for (int t = 0; t < 16; ++t) {
        int idx = tid + t * 256;
        int d = idx & 63, e = idx >> 6;
        float v = d_wP[g*4096 + d * 64 + e];
        if (d == e) v += d_a[n * C_ + g * 64 + d];
        *(float2*)&Md[e * 130 + 2 * d] = make_float2(v, v);
    }

    float* bufs[2] = { xs0, xs1 };
    int buf = 0;
    for (int t = 0; t < 8; ++t) {
        CP_WAIT0();
        __syncthreads();
        if (t < 7) {
            const float* src = base + (t + 1) * 64;
            float* db = bufs[buf ^ 1];
            #pragma unroll
            for (int k = 0; k < 4; ++k) {
                int pos = tid + k * 256;
                int c = pos >> 4, s4 = pos & 15;
                cpa16(db + c * 68 + s4 * 4, src + (size_t)c * HW_ + s4 * 4);
            }
            CP_COMMIT();
        }
        ull acc[4][2] = {};
        const ull* xa = (const ull*)bufs[buf];   // stride 34
        const ull* Ma = (const ull*)Md;          // stride 65
        #pragma unroll 4
        for (int e = 0; e < 64; ++e) {
            ull b0 = xa[e*34 + tx], b1 = xa[e*34 + tx + 16];
            ull a0 = Ma[e*65 + ty],      a1 = Ma[e*65 + ty + 16];
            ull a2 = Ma[e*65 + ty + 32], a3 = Ma[e*65 + ty + 48];
            fma2(acc[0][0], a0, b0); fma2(acc[0][1], a0, b1);
            fma2(acc[1][0], a1, b0); fma2(acc[1][1], a1, b1);
            fma2(acc[2][0], a2, b0); fma2(acc[2][1], a2, b1);
            fma2(acc[3][0], a3, b0); fma2(acc[3][1], a3, b1);
        }
        float* dst = obase + t * 64;
        #pragma unroll
        for (int i = 0; i < 4; ++i) {
            int d = ty + 16 * i;
            *(float2*)(dst + (size_t)d * HW_ + 2*tx)      = u2f(acc[i][0]);
            *(float2*)(dst + (size_t)d * HW_ + 2*tx + 32) = u2f(acc[i][1]);
        }
        buf ^= 1;
    }
}

// ---------------- launch ----------------
extern "C" void kernel_launch(void* const* d_in, const int* in_sizes, int n_in,
                              void* d_out, int out_size) {
    const float* X   = (const float*)d_in[0];
    const float* fc1 = (const float*)d_in[1];
    const float* lng = (const float*)d_in[2];
    const float* lnb = (const float*)d_in[3];
    const float* fc2 = (const float*)d_in[4];
    const float* xw  = (const float*)d_in[5];
    float* out = (float*)d_out;

    static bool attr_set = false;
    if (!attr_set) {
        cudaFuncSetAttribute(k_tail,  cudaFuncAttributeMaxDynamicSharedMemorySize, 69632);
        cudaFuncSetAttribute(k_apply, cudaFuncAttributeMaxDynamicSharedMemorySize, 69632);
        attr_set = true;
    }

    k_zero <<<64, 256>>>();
    k_gram <<<dim3(4, 32, 4), 256>>>(X);
    k_tail <<<36, 512, 67584>>>(fc1, lng, lnb, fc2, xw);
    k_apply<<<dim3(8, 32, 4), 256, 68096>>>(X, out);
}

// round 7
// speedup vs baseline: 1.3089x; 1.1422x over previous
#include <cuda_runtime.h>
#include <math.h>

#define N_   32
#define C_   256
#define HW_  4096
#define G_   4
#define D_   64
#define MTOT 131072.0f
#define EPSW 1e-5f
#define LNEPS 1e-5f

typedef unsigned long long ull;

__device__ __forceinline__ void fma2(ull& d, ull a, ull b) {
    asm("fma.rn.f32x2 %0, %1, %2, %0;" : "+l"(d) : "l"(a), "l"(b));
}
__device__ __forceinline__ void add2(ull& d, ull a) {
    asm("add.rn.f32x2 %0, %0, %1;" : "+l"(d) : "l"(a));
}
__device__ __forceinline__ float2 u2f(ull v) {
    float2 r;
    asm("mov.b64 {%0,%1}, %2;" : "=f"(r.x), "=f"(r.y) : "l"(v));
    return r;
}
__device__ __forceinline__ ull dupf(float f) {
    ull r;
    asm("mov.b64 %0, {%1, %1};" : "=l"(r) : "f"(f));
    return r;
}
__device__ __forceinline__ void cpa16(void* sdst, const void* gsrc) {
    unsigned s = (unsigned)__cvta_generic_to_shared(sdst);
    asm volatile("cp.async.ca.shared.global [%0], [%1], 16;" :: "r"(s), "l"(gsrc));
}
#define CP_COMMIT() asm volatile("cp.async.commit_group;")
#define CP_WAIT0()  asm volatile("cp.async.wait_group 0;")

// ---------------- device scratch ----------------
__device__ float d_sum  [N_*C_];
__device__ float d_sumsq[N_*C_];
__device__ float d_gram [G_*D_*D_];
__device__ float d_a    [N_*C_];
__device__ float d_wP   [G_*D_*D_];

// ---------------- K0: zero accumulators ----------------
__global__ void k_zero() {
    int i = blockIdx.x * blockDim.x + threadIdx.x;
    if (i < N_*C_) { d_sum[i] = 0.0f; d_sumsq[i] = 0.0f; }
    if (i < G_*D_*D_) d_gram[i] = 0.0f;
}

// ---------------- K1: gram + fused row stats -------------------------------
// grid (chunk=4, n=32, g=4), 256 thr, 64-pos tiles, double-buffered cp.async.
// Rows 68 floats = 17 float4 (16 data + pad). All compute loads are LDS.128
// (ulonglong2): 8 loads per 32 FFMA2. Quarter-warp banks 4*tx%32 distinct.
__global__ void __launch_bounds__(256) k_gram(const float* __restrict__ X) {
    __shared__ __align__(16) float xs[2][D_ * 68];   // 34816 B
    __shared__ float rs[256], rs2[256];
    int chunk = blockIdx.x, n = blockIdx.y, g = blockIdx.z;
    int tid = threadIdx.x;
    int tx = tid & 15, ty = tid >> 4;
    int cs = tid & 63, q = tid >> 6;
    const float* base = X + ((size_t)n * C_ + (size_t)g * D_) * HW_ + chunk * 1024;

    ull acc[4][4] = {};
    ull s_acc = 0ull, s2_acc = 0ull;

    {   // prologue: tile 0 -> buf 0 (64 rows x 16 float4)
        #pragma unroll
        for (int k = 0; k < 4; ++k) {
            int pos = tid + k * 256;
            int c = pos >> 4, s4 = pos & 15;
            cpa16(&xs[0][c * 68 + s4 * 4], base + (size_t)c * HW_ + s4 * 4);
        }
        CP_COMMIT();
    }

    int buf = 0;
    for (int t = 0; t < 16; ++t) {
        CP_WAIT0();
        __syncthreads();
        if (t < 15) {
            const float* src = base + (t + 1) * 64;
            #pragma unroll
            for (int k = 0; k < 4; ++k) {
                int pos = tid + k * 256;
                int c = pos >> 4, s4 = pos & 15;
                cpa16(&xs[buf ^ 1][c * 68 + s4 * 4], src + (size_t)c * HW_ + s4 * 4);
            }
            CP_COMMIT();
        }
        const ulonglong2* xa = (const ulonglong2*)xs[buf];   // row stride 17 u2
        #pragma unroll 2
        for (int u = 0; u < 16; ++u) {
            ulonglong2 A0 = xa[(ty     )*17 + u], A1 = xa[(ty + 16)*17 + u];
            ulonglong2 A2 = xa[(ty + 32)*17 + u], A3 = xa[(ty + 48)*17 + u];
            ulonglong2 B0 = xa[(tx     )*17 + u], B1 = xa[(tx + 16)*17 + u];
            ulonglong2 B2 = xa[(tx + 32)*17 + u], B3 = xa[(tx + 48)*17 + u];
            fma2(acc[0][0], A0.x, B0.x); fma2(acc[0][0], A0.y, B0.y);
            fma2(acc[0][1], A0.x, B1.x); fma2(acc[0][1], A0.y, B1.y);
            fma2(acc[0][2], A0.x, B2.x); fma2(acc[0][2], A0.y, B2.y);
            fma2(acc[0][3], A0.x, B3.x); fma2(acc[0][3], A0.y, B3.y);
            fma2(acc[1][0], A1.x, B0.x); fma2(acc[1][0], A1.y, B0.y);
            fma2(acc[1][1], A1.x, B1.x); fma2(acc[1][1], A1.y, B1.y);
            fma2(acc[1][2], A1.x, B2.x); fma2(acc[1][2], A1.y, B2.y);
            fma2(acc[1][3], A1.x, B3.x); fma2(acc[1][3], A1.y, B3.y);
            fma2(acc[2][0], A2.x, B0.x); fma2(acc[2][0], A2.y, B0.y);
            fma2(acc[2][1], A2.x, B1.x); fma2(acc[2][1], A2.y, B1.y);
            fma2(acc[2][2], A2.x, B2.x); fma2(acc[2][2], A2.y, B2.y);
            fma2(acc[2][3], A2.x, B3.x); fma2(acc[2][3], A2.y, B3.y);
            fma2(acc[3][0], A3.x, B0.x); fma2(acc[3][0], A3.y, B0.y);
            fma2(acc[3][1], A3.x, B1.x); fma2(acc[3][1], A3.y, B1.y);
            fma2(acc[3][2], A3.x, B2.x); fma2(acc[3][2], A3.y, B2.y);
            fma2(acc[3][3], A3.x, B3.x); fma2(acc[3][3], A3.y, B3.y);
        }
        // fused per-channel stats: thread covers channel cs, float4 quarter q
        #pragma unroll
        for (int u = 4 * q; u < 4 * q + 4; ++u) {
            ulonglong2 v = xa[cs * 17 + u];
            add2(s_acc, v.x);  add2(s_acc, v.y);
            fma2(s2_acc, v.x, v.x); fma2(s2_acc, v.y, v.y);
        }
        buf ^= 1;
    }

    float2 sv = u2f(s_acc), s2v = u2f(s2_acc);
    rs[tid] = sv.x + sv.y; rs2[tid] = s2v.x + s2v.y;
    __syncthreads();
    if (tid < 64) {
        float a = rs[tid] + rs[tid+64] + rs[tid+128] + rs[tid+192];
        float b = rs2[tid] + rs2[tid+64] + rs2[tid+128] + rs2[tid+192];
        atomicAdd(&d_sum  [n * C_ + g * 64 + tid], a);
        atomicAdd(&d_sumsq[n * C_ + g * 64 + tid], b);
    }
    float* gp = d_gram + g * D_ * D_;
    #pragma unroll
    for (int i = 0; i < 4; ++i)
        #pragma unroll
        for (int j = 0; j < 4; ++j) {
            float2 f = u2f(acc[i][j]);
            atomicAdd(&gp[(ty + 16*i) * D_ + tx + 16*j], f.x + f.y);
        }
}

// ---------------- K2: fused newton (blocks 0-3) + mlp (blocks 4-35) --------
__device__ __forceinline__ void mm64t(float* Cm, const float* A, const float* B,
                                      int tx, int ty) {
    float acc[2][4] = {};
    #pragma unroll 4
    for (int k = 0; k < 64; ++k) {
        float a0 = A[ty*66 + k], a1 = A[(ty + 32)*66 + k];
        float b0 = B[k*66 + tx],      b1 = B[k*66 + tx + 16];
        float b2 = B[k*66 + tx + 32], b3 = B[k*66 + tx + 48];
        acc[0][0] += a0*b0; acc[0][1] += a0*b1; acc[0][2] += a0*b2; acc[0][3] += a0*b3;
        acc[1][0] += a1*b0; acc[1][1] += a1*b1; acc[1][2] += a1*b2; acc[1][3] += a1*b3;
    }
    #pragma unroll
    for (int i = 0; i < 2; ++i)
        #pragma unroll
        for (int j = 0; j < 4; ++j)
            Cm[(ty + 32*i)*66 + tx + 16*j] = acc[i][j];
}

__global__ void __launch_bounds__(512) k_tail(const float* __restrict__ fc1,
                                              const float* __restrict__ lng,
                                              const float* __restrict__ lnb,
                                              const float* __restrict__ fc2,
                                              const float* __restrict__ xw) {
    extern __shared__ float sm[];
    int blk = blockIdx.x, tid = threadIdx.x;
    float w = 1.0f / (1.0f + expf(-xw[0]));

    if (blk < 4) {
        float* SigN = sm;
        float* P    = sm + 4224;
        float* T1   = sm + 8448;
        float* T2   = sm + 12672;
        __shared__ float mu_s[64];
        __shared__ float s_invtr;
        int g = blk;
        int tx = tid & 15, ty = tid >> 4;

        if (tid < 64) {
            float m = 0.0f;
            #pragma unroll
            for (int n = 0; n < N_; ++n) m += d_sum[n * C_ + g * 64 + tid];
            mu_s[tid] = m * (1.0f / MTOT);
        }
        __syncthreads();

        for (int t = 0; t < 8; ++t) {
            int idx = tid + t * 512;
            int d = idx >> 6, e = idx & 63;
            float v = EPSW * (d_gram[g*4096 + idx] - MTOT * mu_s[d] * mu_s[e]);
            if (d == e) v += 1.0f / MTOT;
            T1[d*66 + e] = v;
        }
        __syncthreads();
        if (tid == 0) {
            float tr = 0.0f;
            for (int d = 0; d < 64; ++d) tr += T1[d*66 + d];
            s_invtr = 1.0f / tr;
        }
        __syncthreads();
        float invtr = s_invtr;
        for (int t = 0; t < 8; ++t) {        // P1 = -0.5I + 1.5 SigN (P0 = I)
            int idx = tid + t * 512;
            int d = idx >> 6, e = idx & 63;
            float s = T1[d*66 + e] * invtr;
            SigN[d*66 + e] = s;
            P[d*66 + e] = 1.5f * s + ((d == e) ? -0.5f : 0.0f);
        }
        __syncthreads();
        for (int it = 0; it < 2; ++it) {
            mm64t(T1, P, P, tx, ty);     __syncthreads();
            mm64t(T2, T1, P, tx, ty);    __syncthreads();
            mm64t(T1, T2, SigN, tx, ty); __syncthreads();
            for (int t = 0; t < 8; ++t) {
                int idx = tid + t * 512;
                int d = idx >> 6, e = idx & 63;
                P[d*66 + e] = -0.5f * P[d*66 + e] + 1.5f * T1[d*66 + e];
            }
            __syncthreads();
        }
        for (int t = 0; t < 8; ++t) {
            int idx = tid + t * 512;
            int d = idx >> 6, e = idx & 63;
            d_wP[g*4096 + idx] = w * P[d*66 + e];
        }
    } else {
        int n = blk - 4;
        float* xv  = sm;          // 256
        float* h   = sm + 256;    // 64
        float* red = sm + 320;    // 512
        __shared__ float s_mu, s_inv, s_coef;
        int wi = tid >> 5, lane = tid & 31;

        float acc = 0.0f;
        for (int i = tid; i < N_*C_; i += 512) {
            float s = d_sum[i], s2 = d_sumsq[i];
            acc += (s2 - s * s * (1.0f / HW_)) * (1.0f / (HW_ - 1));
        }
        red[tid] = acc;
        if (tid < 256) {
            float s = d_sum[n * C_ + tid], s2 = d_sumsq[n * C_ + tid];
            xv[tid] = (s2 - s * s * (1.0f / HW_)) * (1.0f / (HW_ - 1));
        }
        __syncthreads();
        for (int off = 256; off; off >>= 1) {
            if (tid < off) red[tid] += red[tid + off];
            __syncthreads();
        }
        if (tid == 0)
            s_coef = (1.0f - w) / sqrtf(red[0] * (1.0f / (N_*C_)));

        #pragma unroll
        for (int jj = 0; jj < 4; ++jj) {
            int j = wi * 4 + jj;
            float a = 0.0f;
            #pragma unroll
            for (int s = 0; s < 8; ++s)
                a += fc1[j * C_ + lane + 32 * s] * xv[lane + 32 * s];
            #pragma unroll
            for (int o = 16; o; o >>= 1) a += __shfl_xor_sync(0xffffffffu, a, o);
            if (lane == 0) h[j] = a;
        }
        __syncthreads();

        if (wi == 0) {
            float v0 = h[lane], v1 = h[lane + 32];
            float s = v0 + v1, s2 = v0*v0 + v1*v1;
            #pragma unroll
            for (int o = 16; o; o >>= 1) {
                s  += __shfl_xor_sync(0xffffffffu, s,  o);
                s2 += __shfl_xor_sync(0xffffffffu, s2, o);
            }
            if (lane == 0) {
                float mu = s * (1.0f / D_);
                float var = s2 * (1.0f / D_) - mu * mu;
                s_mu = mu; s_inv = rsqrtf(var + LNEPS);
            }
        }
        __syncthreads();
        if (tid < 64) {
            float v = (h[tid] - s_mu) * s_inv * lng[tid] + lnb[tid];
            h[tid] = v > 0.0f ? v : 0.0f;
        }
        __syncthreads();

        float coef = s_coef;
        #pragma unroll
        for (int k = 0; k < 16; ++k) {
            int c = wi + 16 * k;
            float a = fc2[c * D_ + lane] * h[lane]
                    + fc2[c * D_ + lane + 32] * h[lane + 32];
            #pragma unroll
            for (int o = 16; o; o >>= 1) a += __shfl_xor_sync(0xffffffffu, a, o);
            if (lane == 0) d_a[n * C_ + c] = coef / (1.0f + expf(-a));
        }
    }
}

// ---------------- K3: out = (wP[g] + diag(a[n])) @ x -----------------------
// grid (chunk=8, n=32, g=4), 256 thr, 128-pos tiles (4 per chunk), 4d x 8s.
// d0 = 4*ty (consecutive rows): a-operand = ONE LDS.128 of Mt[e][4ty..4ty+3]
// (M stored transposed, rows padded to 68) + 4 mov.b64 dups.
// b-operand = 2 LDS.128 (xs rows 132 floats; quarter-warp banks 4tx distinct).
// Per e: 3 LDS + 4 ALU per 16 FFMA2.
__global__ void __launch_bounds__(256) k_apply(const float* __restrict__ X,
                                               float* __restrict__ out) {
    extern __shared__ __align__(16) float sm2[];
    float* xs0 = sm2;                  // 64*132 = 8448 floats
    float* xs1 = sm2 + 8448;
    float* Mt  = sm2 + 16896;          // 64*68  = 4352 floats
    int chunk = blockIdx.x, n = blockIdx.y, g = blockIdx.z;
    int tid = threadIdx.x;
    int tx = tid & 15, ty = tid >> 4;
    int d0 = 4 * ty;

    const float* base  = X   + ((size_t)n * C_ + (size_t)g * D_) * HW_ + chunk * 512;
    float*       obase = out + ((size_t)n * C_ + (size_t)g * D_) * HW_ + chunk * 512;

    {   // prologue copy tile 0 (64 rows x 32 float4)
        #pragma unroll
        for (int k = 0; k < 8; ++k) {
            int pos = tid + k * 256;
            int c = pos >> 5, s4 = pos & 31;
            cpa16(xs0 + c * 132 + s4 * 4, base + (size_t)c * HW_ + s4 * 4);
        }
        CP_COMMIT();
    }
    // build Mt[e][d] = M[d][e] while copy 0 is in flight
    for (int t = 0; t < 16; ++t) {
        int idx = tid + t * 256;
        int d = idx & 63, e = idx >> 6;
        float v = d_wP[g*4096 + d * 64 + e];
        if (d == e) v += d_a[n * C_ + g * 64 + d];
        Mt[e * 68 + d] = v;
    }

    float* bufs[2] = { xs0, xs1 };
    int buf = 0;
    for (int t = 0; t < 4; ++t) {
        CP_WAIT0();
        __syncthreads();
        if (t < 3) {
            const float* src = base + (t + 1) * 128;
            float* db = bufs[buf ^ 1];
            #pragma unroll
            for (int k = 0; k < 8; ++k) {
                int pos = tid + k * 256;
                int c = pos >> 5, s4 = pos & 31;
                cpa16(db + c * 132 + s4 * 4, src + (size_t)c * HW_ + s4 * 4);
            }
            CP_COMMIT();
        }
        ull acc[4][4] = {};
        const ulonglong2* xa = (const ulonglong2*)bufs[buf];  // row stride 33 u2
        const float4*     ma = (const float4*)Mt;             // row stride 17 f4
        #pragma unroll 4
        for (int e = 0; e < 64; ++e) {
            float4 m = ma[e * 17 + ty];
            ulonglong2 B0 = xa[e * 33 + tx];
            ulonglong2 B1 = xa[e * 33 + tx + 16];
            ull a0 = dupf(m.x), a1 = dupf(m.y), a2 = dupf(m.z), a3 = dupf(m.w);
            fma2(acc[0][0], a0, B0.x); fma2(acc[0][1], a0, B0.y);
            fma2(acc[0][2], a0, B1.x); fma2(acc[0][3], a0, B1.y);
            fma2(acc[1][0], a1, B0.x); fma2(acc[1][1], a1, B0.y);
            fma2(acc[1][2], a1, B1.x); fma2(acc[1][3], a1, B1.y);
            fma2(acc[2][0], a2, B0.x); fma2(acc[2][1], a2, B0.y);
            fma2(acc[2][2], a2, B1.x); fma2(acc[2][3], a2, B1.y);
            fma2(acc[3][0], a3, B0.x); fma2(acc[3][1], a3, B0.y);
            fma2(acc[3][2], a3, B1.x); fma2(acc[3][3], a3, B1.y);
        }
        float* dst = obase + t * 128;
        #pragma unroll
        for (int i = 0; i < 4; ++i) {
            float* drow = dst + (size_t)(d0 + i) * HW_;
            float2 r0 = u2f(acc[i][0]), r1 = u2f(acc[i][1]);
            float2 r2 = u2f(acc[i][2]), r3 = u2f(acc[i][3]);
            *(float4*)(drow + 4 * tx)      = make_float4(r0.x, r0.y, r1.x, r1.y);
            *(float4*)(drow + 4 * tx + 64) = make_float4(r2.x, r2.y, r3.x, r3.y);
        }
        buf ^= 1;
    }
}

// ---------------- launch ----------------
extern "C" void kernel_launch(void* const* d_in, const int* in_sizes, int n_in,
                              void* d_out, int out_size) {
    const float* X   = (const float*)d_in[0];
    const float* fc1 = (const float*)d_in[1];
    const float* lng = (const float*)d_in[2];
    const float* lnb = (const float*)d_in[3];
    const float* fc2 = (const float*)d_in[4];
    const float* xw  = (const float*)d_in[5];
    float* out = (float*)d_out;

    static bool attr_set = false;
    if (!attr_set) {
        cudaFuncSetAttribute(k_tail,  cudaFuncAttributeMaxDynamicSharedMemorySize, 69632);
        cudaFuncSetAttribute(k_apply, cudaFuncAttributeMaxDynamicSharedMemorySize, 86016);
        attr_set = true;
    }

    k_zero <<<64, 256>>>();
    k_gram <<<dim3(4, 32, 4), 256>>>(X);
    k_tail <<<36, 512, 67584>>>(fc1, lng, lnb, fc2, xw);
    k_apply<<<dim3(8, 32, 4), 256, 85504>>>(X, out);
}

// round 8
// speedup vs baseline: 1.3919x; 1.0634x over previous
#include <cuda_runtime.h>
#include <math.h>

#define N_   32
#define C_   256
#define HW_  4096
#define G_   4
#define D_   64
#define MTOT 131072.0f
#define EPSW 1e-5f
#define LNEPS 1e-5f

typedef unsigned long long ull;

__device__ __forceinline__ void fma2(ull& d, ull a, ull b) {
    asm("fma.rn.f32x2 %0, %1, %2, %0;" : "+l"(d) : "l"(a), "l"(b));
}
__device__ __forceinline__ void add2(ull& d, ull a) {
    asm("add.rn.f32x2 %0, %0, %1;" : "+l"(d) : "l"(a));
}
__device__ __forceinline__ float2 u2f(ull v) {
    float2 r;
    asm("mov.b64 {%0,%1}, %2;" : "=f"(r.x), "=f"(r.y) : "l"(v));
    return r;
}
__device__ __forceinline__ ull dupf(float f) {
    ull r;
    asm("mov.b64 %0, {%1, %1};" : "=l"(r) : "f"(f));
    return r;
}
__device__ __forceinline__ void cpa16(void* sdst, const void* gsrc) {
    unsigned s = (unsigned)__cvta_generic_to_shared(sdst);
    asm volatile("cp.async.ca.shared.global [%0], [%1], 16;" :: "r"(s), "l"(gsrc));
}
#define CP_COMMIT() asm volatile("cp.async.commit_group;")
#define CP_WAIT0()  asm volatile("cp.async.wait_group 0;")

// ---------------- device scratch ----------------
__device__ float d_sum  [N_*C_];
__device__ float d_sumsq[N_*C_];
__device__ float d_gram [G_*D_*D_];
__device__ float d_a    [N_*C_];
__device__ float d_wP   [G_*D_*D_];

// ---------------- K0: zero accumulators ----------------
__global__ void k_zero() {
    int i = blockIdx.x * blockDim.x + threadIdx.x;
    if (i < N_*C_) { d_sum[i] = 0.0f; d_sumsq[i] = 0.0f; }
    if (i < G_*D_*D_) d_gram[i] = 0.0f;
}

// ---------------- K1: gram (SYMMETRIC) + fused row stats -------------------
// grid (chunk=4, n=32, g=4), 256 thr, 64-pos tiles, dbuf cp.async.
// Symmetric: compute only tile pairs (i,j) with j>=i (10 of 16 accumulators);
// off-diagonal blocks mirrored in the atomic epilogue. Diagonal blocks (i==j)
// cover both triangles exactly once across threads.
__global__ void __launch_bounds__(256, 3) k_gram(const float* __restrict__ X) {
    __shared__ __align__(16) float xs[2][D_ * 68];   // 34816 B
    __shared__ float rs[256], rs2[256];
    int chunk = blockIdx.x, n = blockIdx.y, g = blockIdx.z;
    int tid = threadIdx.x;
    int tx = tid & 15, ty = tid >> 4;
    int cs = tid & 63, q = tid >> 6;
    const float* base = X + ((size_t)n * C_ + (size_t)g * D_) * HW_ + chunk * 1024;

    // order: (0,0)(0,1)(0,2)(0,3)(1,1)(1,2)(1,3)(2,2)(2,3)(3,3)
    ull a00=0,a01=0,a02=0,a03=0,a11=0,a12=0,a13=0,a22=0,a23=0,a33=0;
    ull s_acc = 0ull, s2_acc = 0ull;

    {   // prologue: tile 0 -> buf 0 (64 rows x 16 float4)
        #pragma unroll
        for (int k = 0; k < 4; ++k) {
            int pos = tid + k * 256;
            int c = pos >> 4, s4 = pos & 15;
            cpa16(&xs[0][c * 68 + s4 * 4], base + (size_t)c * HW_ + s4 * 4);
        }
        CP_COMMIT();
    }

    int buf = 0;
    for (int t = 0; t < 16; ++t) {
        CP_WAIT0();
        __syncthreads();
        if (t < 15) {
            const float* src = base + (t + 1) * 64;
            #pragma unroll
            for (int k = 0; k < 4; ++k) {
                int pos = tid + k * 256;
                int c = pos >> 4, s4 = pos & 15;
                cpa16(&xs[buf ^ 1][c * 68 + s4 * 4], src + (size_t)c * HW_ + s4 * 4);
            }
            CP_COMMIT();
        }
        const ulonglong2* xa = (const ulonglong2*)xs[buf];   // row stride 17 u2
        #pragma unroll 4
        for (int u = 0; u < 16; ++u) {
            ulonglong2 A0 = xa[(ty     )*17 + u], A1 = xa[(ty + 16)*17 + u];
            ulonglong2 A2 = xa[(ty + 32)*17 + u], A3 = xa[(ty + 48)*17 + u];
            ulonglong2 B0 = xa[(tx     )*17 + u], B1 = xa[(tx + 16)*17 + u];
            ulonglong2 B2 = xa[(tx + 32)*17 + u], B3 = xa[(tx + 48)*17 + u];
            fma2(a00, A0.x, B0.x); fma2(a00, A0.y, B0.y);
            fma2(a01, A0.x, B1.x); fma2(a01, A0.y, B1.y);
            fma2(a02, A0.x, B2.x); fma2(a02, A0.y, B2.y);
            fma2(a03, A0.x, B3.x); fma2(a03, A0.y, B3.y);
            fma2(a11, A1.x, B1.x); fma2(a11, A1.y, B1.y);
            fma2(a12, A1.x, B2.x); fma2(a12, A1.y, B2.y);
            fma2(a13, A1.x, B3.x); fma2(a13, A1.y, B3.y);
            fma2(a22, A2.x, B2.x); fma2(a22, A2.y, B2.y);
            fma2(a23, A2.x, B3.x); fma2(a23, A2.y, B3.y);
            fma2(a33, A3.x, B3.x); fma2(a33, A3.y, B3.y);
        }
        // fused per-channel stats
        #pragma unroll
        for (int u = 4 * q; u < 4 * q + 4; ++u) {
            ulonglong2 v = xa[cs * 17 + u];
            add2(s_acc, v.x);  add2(s_acc, v.y);
            fma2(s2_acc, v.x, v.x); fma2(s2_acc, v.y, v.y);
        }
        buf ^= 1;
    }

    float2 sv = u2f(s_acc), s2v = u2f(s2_acc);
    rs[tid] = sv.x + sv.y; rs2[tid] = s2v.x + s2v.y;
    __syncthreads();
    if (tid < 64) {
        float a = rs[tid] + rs[tid+64] + rs[tid+128] + rs[tid+192];
        float b = rs2[tid] + rs2[tid+64] + rs2[tid+128] + rs2[tid+192];
        atomicAdd(&d_sum  [n * C_ + g * 64 + tid], a);
        atomicAdd(&d_sumsq[n * C_ + g * 64 + tid], b);
    }
    float* gp = d_gram + g * D_ * D_;
    {
        ull accs[10] = {a00,a01,a02,a03,a11,a12,a13,a22,a23,a33};
        const int II[10] = {0,0,0,0,1,1,1,2,2,3};
        const int JJ[10] = {0,1,2,3,1,2,3,2,3,3};
        #pragma unroll
        for (int k = 0; k < 10; ++k) {
            float2 f = u2f(accs[k]);
            float v = f.x + f.y;
            int r = ty + 16 * II[k], c = tx + 16 * JJ[k];
            atomicAdd(&gp[r * D_ + c], v);
            if (II[k] != JJ[k]) atomicAdd(&gp[c * D_ + r], v);
        }
    }
}

// ---------------- K2: fused newton (blocks 0-3) + mlp (blocks 4-35) --------
__device__ __forceinline__ void mm64t(float* Cm, const float* A, const float* B,
                                      int tx, int ty) {
    float acc[2][4] = {};
    #pragma unroll 4
    for (int k = 0; k < 64; ++k) {
        float a0 = A[ty*66 + k], a1 = A[(ty + 32)*66 + k];
        float b0 = B[k*66 + tx],      b1 = B[k*66 + tx + 16];
        float b2 = B[k*66 + tx + 32], b3 = B[k*66 + tx + 48];
        acc[0][0] += a0*b0; acc[0][1] += a0*b1; acc[0][2] += a0*b2; acc[0][3] += a0*b3;
        acc[1][0] += a1*b0; acc[1][1] += a1*b1; acc[1][2] += a1*b2; acc[1][3] += a1*b3;
    }
    #pragma unroll
    for (int i = 0; i < 2; ++i)
        #pragma unroll
        for (int j = 0; j < 4; ++j)
            Cm[(ty + 32*i)*66 + tx + 16*j] = acc[i][j];
}

__global__ void __launch_bounds__(512) k_tail(const float* __restrict__ fc1,
                                              const float* __restrict__ lng,
                                              const float* __restrict__ lnb,
                                              const float* __restrict__ fc2,
                                              const float* __restrict__ xw) {
    extern __shared__ float sm[];
    int blk = blockIdx.x, tid = threadIdx.x;
    float w = 1.0f / (1.0f + expf(-xw[0]));

    if (blk < 4) {
        float* SigN = sm;
        float* P    = sm + 4224;
        float* T1   = sm + 8448;
        float* T2   = sm + 12672;
        __shared__ float mu_s[64];
        __shared__ float s_invtr;
        int g = blk;
        int tx = tid & 15, ty = tid >> 4;

        if (tid < 64) {
            float m = 0.0f;
            #pragma unroll
            for (int n = 0; n < N_; ++n) m += d_sum[n * C_ + g * 64 + tid];
            mu_s[tid] = m * (1.0f / MTOT);
        }
        __syncthreads();

        for (int t = 0; t < 8; ++t) {
            int idx = tid + t * 512;
            int d = idx >> 6, e = idx & 63;
            float v = EPSW * (d_gram[g*4096 + idx] - MTOT * mu_s[d] * mu_s[e]);
            if (d == e) v += 1.0f / MTOT;
            T1[d*66 + e] = v;
        }
        __syncthreads();
        if (tid == 0) {
            float tr = 0.0f;
            for (int d = 0; d < 64; ++d) tr += T1[d*66 + d];
            s_invtr = 1.0f / tr;
        }
        __syncthreads();
        float invtr = s_invtr;
        for (int t = 0; t < 8; ++t) {        // P1 = -0.5I + 1.5 SigN (P0 = I)
            int idx = tid + t * 512;
            int d = idx >> 6, e = idx & 63;
            float s = T1[d*66 + e] * invtr;
            SigN[d*66 + e] = s;
            P[d*66 + e] = 1.5f * s + ((d == e) ? -0.5f : 0.0f);
        }
        __syncthreads();
        for (int it = 0; it < 2; ++it) {
            mm64t(T1, P, P, tx, ty);     __syncthreads();
            mm64t(T2, T1, P, tx, ty);    __syncthreads();
            mm64t(T1, T2, SigN, tx, ty); __syncthreads();
            for (int t = 0; t < 8; ++t) {
                int idx = tid + t * 512;
                int d = idx >> 6, e = idx & 63;
                P[d*66 + e] = -0.5f * P[d*66 + e] + 1.5f * T1[d*66 + e];
            }
            __syncthreads();
        }
        for (int t = 0; t < 8; ++t) {
            int idx = tid + t * 512;
            int d = idx >> 6, e = idx & 63;
            d_wP[g*4096 + idx] = w * P[d*66 + e];
        }
    } else {
        int n = blk - 4;
        float* xv  = sm;          // 256
        float* h   = sm + 256;    // 64
        float* red = sm + 320;    // 512
        __shared__ float s_mu, s_inv, s_coef;
        int wi = tid >> 5, lane = tid & 31;

        float acc = 0.0f;
        for (int i = tid; i < N_*C_; i += 512) {
            float s = d_sum[i], s2 = d_sumsq[i];
            acc += (s2 - s * s * (1.0f / HW_)) * (1.0f / (HW_ - 1));
        }
        red[tid] = acc;
        if (tid < 256) {
            float s = d_sum[n * C_ + tid], s2 = d_sumsq[n * C_ + tid];
            xv[tid] = (s2 - s * s * (1.0f / HW_)) * (1.0f / (HW_ - 1));
        }
        __syncthreads();
        for (int off = 256; off; off >>= 1) {
            if (tid < off) red[tid] += red[tid + off];
            __syncthreads();
        }
        if (tid == 0)
            s_coef = (1.0f - w) / sqrtf(red[0] * (1.0f / (N_*C_)));

        #pragma unroll
        for (int jj = 0; jj < 4; ++jj) {
            int j = wi * 4 + jj;
            float a = 0.0f;
            #pragma unroll
            for (int s = 0; s < 8; ++s)
                a += fc1[j * C_ + lane + 32 * s] * xv[lane + 32 * s];
            #pragma unroll
            for (int o = 16; o; o >>= 1) a += __shfl_xor_sync(0xffffffffu, a, o);
            if (lane == 0) h[j] = a;
        }
        __syncthreads();

        if (wi == 0) {
            float v0 = h[lane], v1 = h[lane + 32];
            float s = v0 + v1, s2 = v0*v0 + v1*v1;
            #pragma unroll
            for (int o = 16; o; o >>= 1) {
                s  += __shfl_xor_sync(0xffffffffu, s,  o);
                s2 += __shfl_xor_sync(0xffffffffu, s2, o);
            }
            if (lane == 0) {
                float mu = s * (1.0f / D_);
                float var = s2 * (1.0f / D_) - mu * mu;
                s_mu = mu; s_inv = rsqrtf(var + LNEPS);
            }
        }
        __syncthreads();
        if (tid < 64) {
            float v = (h[tid] - s_mu) * s_inv * lng[tid] + lnb[tid];
            h[tid] = v > 0.0f ? v : 0.0f;
        }
        __syncthreads();

        float coef = s_coef;
        #pragma unroll
        for (int k = 0; k < 16; ++k) {
            int c = wi + 16 * k;
            float a = fc2[c * D_ + lane] * h[lane]
                    + fc2[c * D_ + lane + 32] * h[lane + 32];
            #pragma unroll
            for (int o = 16; o; o >>= 1) a += __shfl_xor_sync(0xffffffffu, a, o);
            if (lane == 0) d_a[n * C_ + c] = coef / (1.0f + expf(-a));
        }
    }
}

// ---------------- K3: out = (wP[g] + diag(a[n])) @ x -----------------------
// grid (chunk=8, n=32, g=4), 256 thr, 128-pos tiles, 4d x 8s.
// launch_bounds(256,2): ptxas reg budget 128 -> deeper load pipelining.
__global__ void __launch_bounds__(256, 2) k_apply(const float* __restrict__ X,
                                                  float* __restrict__ out) {
    extern __shared__ __align__(16) float sm2[];
    float* xs0 = sm2;                  // 64*132 = 8448 floats
    float* xs1 = sm2 + 8448;
    float* Mt  = sm2 + 16896;          // 64*68  = 4352 floats
    int chunk = blockIdx.x, n = blockIdx.y, g = blockIdx.z;
    int tid = threadIdx.x;
    int tx = tid & 15, ty = tid >> 4;
    int d0 = 4 * ty;

    const float* base  = X   + ((size_t)n * C_ + (size_t)g * D_) * HW_ + chunk * 512;
    float*       obase = out + ((size_t)n * C_ + (size_t)g * D_) * HW_ + chunk * 512;

    {   // prologue copy tile 0 (64 rows x 32 float4)
        #pragma unroll
        for (int k = 0; k < 8; ++k) {
            int pos = tid + k * 256;
            int c = pos >> 5, s4 = pos & 31;
            cpa16(xs0 + c * 132 + s4 * 4, base + (size_t)c * HW_ + s4 * 4);
        }
        CP_COMMIT();
    }
    // build Mt[e][d] = M[d][e] while copy 0 is in flight
    for (int t = 0; t < 16; ++t) {
        int idx = tid + t * 256;
        int d = idx & 63, e = idx >> 6;
        float v = d_wP[g*4096 + d * 64 + e];
        if (d == e) v += d_a[n * C_ + g * 64 + d];
        Mt[e * 68 + d] = v;
    }

    float* bufs[2] = { xs0, xs1 };
    int buf = 0;
    for (int t = 0; t < 4; ++t) {
        CP_WAIT0();
        __syncthreads();
        if (t < 3) {
            const float* src = base + (t + 1) * 128;
            float* db = bufs[buf ^ 1];
            #pragma unroll
            for (int k = 0; k < 8; ++k) {
                int pos = tid + k * 256;
                int c = pos >> 5, s4 = pos & 31;
                cpa16(db + c * 132 + s4 * 4, src + (size_t)c * HW_ + s4 * 4);
            }
            CP_COMMIT();
        }
        ull acc[4][4] = {};
        const ulonglong2* xa = (const ulonglong2*)bufs[buf];  // row stride 33 u2
        const float4*     ma = (const float4*)Mt;             // row stride 17 f4
        #pragma unroll 8
        for (int e = 0; e < 64; ++e) {
            float4 m = ma[e * 17 + ty];
            ulonglong2 B0 = xa[e * 33 + tx];
            ulonglong2 B1 = xa[e * 33 + tx + 16];
            ull a0 = dupf(m.x), a1 = dupf(m.y), a2 = dupf(m.z), a3 = dupf(m.w);
            fma2(acc[0][0], a0, B0.x); fma2(acc[0][1], a0, B0.y);
            fma2(acc[0][2], a0, B1.x); fma2(acc[0][3], a0, B1.y);
            fma2(acc[1][0], a1, B0.x); fma2(acc[1][1], a1, B0.y);
            fma2(acc[1][2], a1, B1.x); fma2(acc[1][3], a1, B1.y);
            fma2(acc[2][0], a2, B0.x); fma2(acc[2][1], a2, B0.y);
            fma2(acc[2][2], a2, B1.x); fma2(acc[2][3], a2, B1.y);
            fma2(acc[3][0], a3, B0.x); fma2(acc[3][1], a3, B0.y);
            fma2(acc[3][2], a3, B1.x); fma2(acc[3][3], a3, B1.y);
        }
        float* dst = obase + t * 128;
        #pragma unroll
        for (int i = 0; i < 4; ++i) {
            float* drow = dst + (size_t)(d0 + i) * HW_;
            float2 r0 = u2f(acc[i][0]), r1 = u2f(acc[i][1]);
            float2 r2 = u2f(acc[i][2]), r3 = u2f(acc[i][3]);
            *(float4*)(drow + 4 * tx)      = make_float4(r0.x, r0.y, r1.x, r1.y);
            *(float4*)(drow + 4 * tx + 64) = make_float4(r2.x, r2.y, r3.x, r3.y);
        }
        buf ^= 1;
    }
}

// ---------------- launch ----------------
extern "C" void kernel_launch(void* const* d_in, const int* in_sizes, int n_in,
                              void* d_out, int out_size) {
    const float* X   = (const float*)d_in[0];
    const float* fc1 = (const float*)d_in[1];
    const float* lng = (const float*)d_in[2];
    const float* lnb = (const float*)d_in[3];
    const float* fc2 = (const float*)d_in[4];
    const float* xw  = (const float*)d_in[5];
    float* out = (float*)d_out;

    static bool attr_set = false;
    if (!attr_set) {
        cudaFuncSetAttribute(k_tail,  cudaFuncAttributeMaxDynamicSharedMemorySize, 69632);
        cudaFuncSetAttribute(k_apply, cudaFuncAttributeMaxDynamicSharedMemorySize, 86016);
        attr_set = true;
    }

    k_zero <<<64, 256>>>();
    k_gram <<<dim3(4, 32, 4), 256>>>(X);
    k_tail <<<36, 512, 67584>>>(fc1, lng, lnb, fc2, xw);
    k_apply<<<dim3(8, 32, 4), 256, 85504>>>(X, out);
}